// round 11
// baseline (speedup 1.0000x reference)
#include <cuda_runtime.h>
#include <cuda_bf16.h>

#define BB 256
#define TT 512
#define DD 64
#define HH 128
#define NBLK 128

// ---------------- device scratch (static, no allocation) ----------------
__device__ uint4 g_w1n[4 * 8 * 512];   // [ksub][kk][s] : W1 pairs, k = ksub*64 + kk*8 + u*2
__device__ uint4 g_whn[4 * 4 * 512];   // [ksub][kk][s] : Whh pairs, k = ksub*32 + kk*8 + u*2
__device__ uint4 g_wih[8 * 512];       // [kk][j]       : Wih pairs, k = kk*8 + u*2
__device__ unsigned g_bar_count = 0;
__device__ unsigned g_bar_flag = 0;

// ---------------- helpers ----------------
typedef unsigned long long ull;

__device__ __forceinline__ float tanh_fast(float x) {
    float y;
    asm("tanh.approx.f32 %0, %1;" : "=f"(y) : "f"(x));
    return y;
}
__device__ __forceinline__ float sigf(float x) { return 1.f / (1.f + __expf(-x)); }
__device__ __forceinline__ float tanh_ex(float x) {
    x = fminf(fmaxf(x, -15.f), 15.f);
    float e = __expf(2.f * x);
    return (e - 1.f) / (e + 1.f);
}
__device__ __forceinline__ float bl(unsigned u) { return __uint_as_float(u << 16); }
__device__ __forceinline__ float braw(unsigned u) { return __uint_as_float(u); }
__device__ __forceinline__ void ffma2(ull& acc, ull ab, ull cd) {
    asm("fma.rn.f32x2 %0, %1, %2, %0;" : "+l"(acc) : "l"(ab), "l"(cd));
}
// pair {even = u<<16, odd = u raw (tail-compensated)}
__device__ __forceinline__ ull bfpair(unsigned u) {
    ull p;
    asm("{\n\t.reg .b32 lo;\n\t"
        "shl.b32 lo, %1, 16;\n\t"
        "mov.b64 %0, {lo, %1};\n\t}" : "=l"(p) : "r"(u));
    return p;
}
__device__ __forceinline__ ull mk_pair(float lo, float hi) {
    ull p;
    asm("mov.b64 %0, {%1, %2};" : "=l"(p) : "f"(lo), "f"(hi));
    return p;
}
__device__ __forceinline__ float pair_lo(ull p) { return __uint_as_float((unsigned)p); }
__device__ __forceinline__ float pair_hi(ull p) { return __uint_as_float((unsigned)(p >> 32)); }
__device__ __forceinline__ float pair_sum(ull p) { return pair_lo(p) + pair_hi(p); }

// Tail-compensated pair pack (see R8): raw reuse of odd elem adds no error.
__device__ __forceinline__ unsigned pack_comp(float we, float wo) {
    __nv_bfloat16 be = __float2bfloat16(we);
    unsigned below = (unsigned)*(unsigned short*)&be;
    unsigned fo = __float_as_uint(wo);
    unsigned c0 = (fo & 0xffff0000u) | below;
    unsigned cm = c0 - 0x10000u;
    unsigned cp = c0 + 0x10000u;
    float d0 = fabsf(__uint_as_float(c0) - wo);
    float dm = fabsf(__uint_as_float(cm) - wo);
    float dp = fabsf(__uint_as_float(cp) - wo);
    unsigned best = c0;
    float bd = d0;
    if (dm < bd) { best = cm; bd = dm; }
    if (dp < bd) { best = cp; }
    return best;
}

// ---------------- smem layout ----------------
#define S2STRIDE 552
#define SM_S2_BYTES (2 * 64 * S2STRIDE * 2)      // 141312
#define SM_WIH_BYTES (8 * 512 * 16)              // 65536
#define SM_FLOATS (576 + 1024 + 1024 + 128 + 128 + 512 + 512 + 512 + 128)  // 4544
#define SM_TOTAL (SM_S2_BYTES + SM_WIH_BYTES + SM_FLOATS * 4)              // 225024

// ---------------- the one kernel ----------------
__global__ void __launch_bounds__(512, 1) fused_kernel(
    const float* __restrict__ din, const float* __restrict__ Wih,
    const float* __restrict__ Whh, const float* __restrict__ bih,
    const float* __restrict__ bhh, const float* __restrict__ W1,
    const float* __restrict__ b1, const float* __restrict__ W2,
    const float* __restrict__ b2, const float* __restrict__ W3,
    const float* __restrict__ b3, float* __restrict__ out) {
    extern __shared__ char smraw[];
    __nv_bfloat16* s2s = (__nv_bfloat16*)smraw;                 // [2*64][552]
    uint4* wihs = (uint4*)(smraw + SM_S2_BYTES);                // [8*512] uint4
    float* fl   = (float*)(smraw + SM_S2_BYTES + SM_WIH_BYTES);
    float* hcp  = fl;                                            // [2][288] padded [h;c]
    float* s1s  = hcp + 576;                                     // [2][512]
    float* zhs  = s1s + 1024;                                    // [2][512]
    float* xs   = zhs + 1024;                                    // [2][64]
    float* es   = xs + 128;                                      // [2][64]
    float* w3s  = es + 128;                                      // [512]
    float* b1s  = w3s + 512;                                     // [512]
    float* bzs  = b1s + 512;                                     // [512]
    float* dinb = bzs + 512;                                     // [2][64]

    const int tid = threadIdx.x;
    const int b0 = blockIdx.x * 2;

    // ======== STAGE 1: pack weights (grid-strided, pair-compensated) ========
    {
        int gidx = blockIdx.x * 512 + tid;
        int gstride = NBLK * 512;
        unsigned* w1d = (unsigned*)g_w1n;
        for (int i = gidx; i < 4 * 8 * 512 * 4; i += gstride) {
            int u = i & 3, s = (i >> 2) & 511, kk = (i >> 11) & 7, ks = i >> 14;
            int k0 = ks * 64 + kk * 8 + u * 2;
            w1d[i] = pack_comp(W1[s * 256 + k0], W1[s * 256 + k0 + 1]);
        }
        unsigned* whd = (unsigned*)g_whn;
        for (int i = gidx; i < 4 * 4 * 512 * 4; i += gstride) {
            int u = i & 3, s = (i >> 2) & 511, kk = (i >> 11) & 3, ks = i >> 13;
            int k0 = ks * 32 + kk * 8 + u * 2;
            whd[i] = pack_comp(Whh[s * 128 + k0], Whh[s * 128 + k0 + 1]);
        }
        unsigned* wid = (unsigned*)g_wih;
        for (int i = gidx; i < 8 * 512 * 4; i += gstride) {
            int u = i & 3, j = (i >> 2) & 511, kk = i >> 11;
            int k0 = kk * 8 + u * 2;
            wid[i] = pack_comp(Wih[j * 64 + k0], Wih[j * 64 + k0 + 1]);
        }
    }
    // grid barrier (128 blocks, all resident)
    __syncthreads();
    if (tid == 0) {
        unsigned f0 = *((volatile unsigned*)&g_bar_flag);
        __threadfence();
        unsigned old = atomicAdd(&g_bar_count, 1);
        if (old == NBLK - 1) {
            g_bar_count = 0;
            __threadfence();
            atomicAdd(&g_bar_flag, 1);
        } else {
            while (*((volatile unsigned*)&g_bar_flag) == f0) { __nanosleep(64); }
        }
        __threadfence();
    }
    __syncthreads();

    // ======== STAGE 2: s2[b,d,s] into SMEM ========
    {
        float* w2st  = (float*)(smraw + SM_S2_BYTES);  // [32][514] staging
        float* dinst = w2st + 32 * 514;                 // [32][64]
        const int lane = tid & 31, sgrp = tid >> 5;
        const int d0 = lane * 2, sbase = sgrp * 32;

        for (int bb = 0; bb < 2; bb++) {
            const int b = b0 + bb;
            ull acc[2][16];
#pragma unroll
            for (int p = 0; p < 16; p++) {
                float2 bp = *(const float2*)(b2 + sbase + 2 * p);
                acc[0][p] = mk_pair(bp.x, bp.y);
                acc[1][p] = acc[0][p];
            }
            for (int tc = 0; tc < 16; tc++) {
                const int t0 = tc * 32;
                __syncthreads();
                for (int i = tid; i < 32 * 512; i += 512) {
                    int tt = i & 31, sl = i >> 5;
                    w2st[tt * 514 + sl] = W2[(size_t)sl * TT + t0 + tt];
                }
                for (int i = tid; i < 32 * 64; i += 512) {
                    int tt = i >> 6, dd = i & 63;
                    dinst[tt * 64 + dd] = din[((size_t)b * TT + t0 + tt) * DD + dd];
                }
                __syncthreads();
#pragma unroll 4
                for (int tt = 0; tt < 32; tt++) {
                    float2 av = *(const float2*)&dinst[tt * 64 + d0];
                    ull ax = mk_pair(av.x, av.x);
                    ull ay = mk_pair(av.y, av.y);
                    const ull* wrow = (const ull*)(w2st + tt * 514 + sbase);
#pragma unroll
                    for (int p = 0; p < 16; p++) {
                        ull wp = wrow[p];
                        ffma2(acc[0][p], wp, ax);
                        ffma2(acc[1][p], wp, ay);
                    }
                }
            }
#pragma unroll
            for (int dl = 0; dl < 2; dl++) {
                unsigned* row = (unsigned*)(s2s + (size_t)(bb * 64 + d0 + dl) * S2STRIDE + sbase);
#pragma unroll
                for (int p = 0; p < 16; p++)
                    row[p] = pack_comp(pair_lo(acc[dl][p]), pair_hi(acc[dl][p]));
            }
        }
    }
    __syncthreads();

    // ======== STAGE 3: init scan constants ========
    w3s[tid] = W3[tid];
    b1s[tid] = b1[tid];
    bzs[tid] = bih[tid] + bhh[tid];
    for (int i = tid; i < 576; i += 512) hcp[i] = 0.f;
    {
        const uint4* src = (const uint4*)g_wih;
        for (int i = tid; i < 8 * 512; i += 512) wihs[i] = src[i];
    }
    __syncthreads();
    const float b3v = b3[0];

    // ======== STAGE 4: the scan ========
    for (int t = 0; t < TT; t++) {
        // prefetch din[., t, .] for phase C (latency hidden behind phase A)
        float dval = 0.f;
        if (tid < 128) {
            int bb = tid >> 6, dd = tid & 63;
            dval = din[((size_t)(b0 + bb) * TT + t) * DD + dd];
        }

        // ---- Phase A (k-split x4): s1 + zh, operands amortized over 4 cols ----
        {
            const int ksub = tid & 3;
            const int scol = tid >> 2;   // 0..127
            const uint4* w1p = (const uint4*)g_w1n + (ksub * 8) * 512 + scol;
            const uint4* whp = (const uint4*)g_whn + (ksub * 4) * 512 + scol;
            const float* h0 = hcp;            // batch0 padded [288]
            const float* h1 = hcp + 288;      // batch1
            ull aS[8], aZ[8];
#pragma unroll
            for (int i = 0; i < 8; i++) { aS[i] = 0ull; aZ[i] = 0ull; }
#pragma unroll 4
            for (int kk = 0; kk < 8; kk++) {
                const int k = ksub * 64 + kk * 8;
                const int kp = k + 4 * (k >> 5);
                ulonglong2 pA = *(const ulonglong2*)(h0 + kp);
                ulonglong2 pB = *(const ulonglong2*)(h0 + kp + 4);
                ulonglong2 qA = *(const ulonglong2*)(h1 + kp);
                ulonglong2 qB = *(const ulonglong2*)(h1 + kp + 4);
#pragma unroll
                for (int c = 0; c < 4; c++) {
                    uint4 w = w1p[kk * 512 + c * 128];
                    ull w01 = bfpair(w.x), w23 = bfpair(w.y);
                    ull w45 = bfpair(w.z), w67 = bfpair(w.w);
                    ffma2(aS[c * 2], w01, pA.x); ffma2(aS[c * 2], w23, pA.y);
                    ffma2(aS[c * 2], w45, pB.x); ffma2(aS[c * 2], w67, pB.y);
                    ffma2(aS[c * 2 + 1], w01, qA.x); ffma2(aS[c * 2 + 1], w23, qA.y);
                    ffma2(aS[c * 2 + 1], w45, qB.x); ffma2(aS[c * 2 + 1], w67, qB.y);
                }
            }
#pragma unroll
            for (int kk = 0; kk < 4; kk++) {
                const int k = ksub * 32 + kk * 8;
                const int kp = k + 4 * (k >> 5);
                ulonglong2 pA = *(const ulonglong2*)(h0 + kp);
                ulonglong2 pB = *(const ulonglong2*)(h0 + kp + 4);
                ulonglong2 qA = *(const ulonglong2*)(h1 + kp);
                ulonglong2 qB = *(const ulonglong2*)(h1 + kp + 4);
#pragma unroll
                for (int c = 0; c < 4; c++) {
                    uint4 v = whp[kk * 512 + c * 128];
                    ull v01 = bfpair(v.x), v23 = bfpair(v.y);
                    ull v45 = bfpair(v.z), v67 = bfpair(v.w);
                    ffma2(aZ[c * 2], v01, pA.x); ffma2(aZ[c * 2], v23, pA.y);
                    ffma2(aZ[c * 2], v45, pB.x); ffma2(aZ[c * 2], v67, pB.y);
                    ffma2(aZ[c * 2 + 1], v01, qA.x); ffma2(aZ[c * 2 + 1], v23, qA.y);
                    ffma2(aZ[c * 2 + 1], v45, qB.x); ffma2(aZ[c * 2 + 1], v67, qB.y);
                }
            }
            float r[16];
#pragma unroll
            for (int i = 0; i < 8; i++) {
                r[i] = pair_sum(aS[i]);
                r[8 + i] = pair_sum(aZ[i]);
            }
#pragma unroll
            for (int i = 0; i < 16; i++) {
                r[i] += __shfl_xor_sync(0xffffffffu, r[i], 1);
                r[i] += __shfl_xor_sync(0xffffffffu, r[i], 2);
            }
            if (ksub == 0) {
#pragma unroll
                for (int c = 0; c < 4; c++) {
                    int s = scol + 128 * c;
                    float bb1 = b1s[s];
                    s1s[s] = r[c * 2] + bb1;
                    s1s[512 + s] = r[c * 2 + 1] + bb1;
                }
            } else if (ksub == 1) {
#pragma unroll
                for (int c = 0; c < 4; c++) {
                    int j = scol + 128 * c;
                    float bz = bzs[j];
                    zhs[j] = r[8 + c * 2] + bz;
                    zhs[512 + j] = r[8 + c * 2 + 1] + bz;
                }
            }
        }
        if (tid < 128) dinb[tid] = dval;
        __syncthreads();

        // ---- Phase B: e[b][d] = sum_s tanh(s1+s2)*w3 + b3 (16 subs x 4 rows) ----
        {
            const int sub = tid & 15, grp = tid >> 4;
            const int bb = grp >> 4, d0 = (grp & 15) * 4;
            const __nv_bfloat16* rowbase = s2s + (size_t)(bb * 64 + d0) * S2STRIDE;
            const uint4* r0 = (const uint4*)(rowbase);
            const uint4* r1 = (const uint4*)(rowbase + S2STRIDE);
            const uint4* r2 = (const uint4*)(rowbase + 2 * S2STRIDE);
            const uint4* r3 = (const uint4*)(rowbase + 3 * S2STRIDE);
            const float4* s1f = (const float4*)(s1s + bb * 512);
            const float4* w3f = (const float4*)w3s;
            float a0 = 0.f, a1 = 0.f, a2 = 0.f, a3 = 0.f;
#pragma unroll
            for (int i = 0; i < 4; i++) {
                const int q = sub + 16 * i;
                float4 sA = s1f[2 * q], sB = s1f[2 * q + 1];
                float4 wA = w3f[2 * q], wB = w3f[2 * q + 1];
                uint4 v0 = r0[q], v1 = r1[q], v2 = r2[q], v3 = r3[q];
                a0 = fmaf(tanh_fast(sA.x + bl(v0.x)), wA.x, a0);
                a0 = fmaf(tanh_fast(sA.y + braw(v0.x)), wA.y, a0);
                a0 = fmaf(tanh_fast(sA.z + bl(v0.y)), wA.z, a0);
                a0 = fmaf(tanh_fast(sA.w + braw(v0.y)), wA.w, a0);
                a0 = fmaf(tanh_fast(sB.x + bl(v0.z)), wB.x, a0);
                a0 = fmaf(tanh_fast(sB.y + braw(v0.z)), wB.y, a0);
                a0 = fmaf(tanh_fast(sB.z + bl(v0.w)), wB.z, a0);
                a0 = fmaf(tanh_fast(sB.w + braw(v0.w)), wB.w, a0);
                a1 = fmaf(tanh_fast(sA.x + bl(v1.x)), wA.x, a1);
                a1 = fmaf(tanh_fast(sA.y + braw(v1.x)), wA.y, a1);
                a1 = fmaf(tanh_fast(sA.z + bl(v1.y)), wA.z, a1);
                a1 = fmaf(tanh_fast(sA.w + braw(v1.y)), wA.w, a1);
                a1 = fmaf(tanh_fast(sB.x + bl(v1.z)), wB.x, a1);
                a1 = fmaf(tanh_fast(sB.y + braw(v1.z)), wB.y, a1);
                a1 = fmaf(tanh_fast(sB.z + bl(v1.w)), wB.z, a1);
                a1 = fmaf(tanh_fast(sB.w + braw(v1.w)), wB.w, a1);
                a2 = fmaf(tanh_fast(sA.x + bl(v2.x)), wA.x, a2);
                a2 = fmaf(tanh_fast(sA.y + braw(v2.x)), wA.y, a2);
                a2 = fmaf(tanh_fast(sA.z + bl(v2.y)), wA.z, a2);
                a2 = fmaf(tanh_fast(sA.w + braw(v2.y)), wA.w, a2);
                a2 = fmaf(tanh_fast(sB.x + bl(v2.z)), wB.x, a2);
                a2 = fmaf(tanh_fast(sB.y + braw(v2.z)), wB.y, a2);
                a2 = fmaf(tanh_fast(sB.z + bl(v2.w)), wB.z, a2);
                a2 = fmaf(tanh_fast(sB.w + braw(v2.w)), wB.w, a2);
                a3 = fmaf(tanh_fast(sA.x + bl(v3.x)), wA.x, a3);
                a3 = fmaf(tanh_fast(sA.y + braw(v3.x)), wA.y, a3);
                a3 = fmaf(tanh_fast(sA.z + bl(v3.y)), wA.z, a3);
                a3 = fmaf(tanh_fast(sA.w + braw(v3.y)), wA.w, a3);
                a3 = fmaf(tanh_fast(sB.x + bl(v3.z)), wB.x, a3);
                a3 = fmaf(tanh_fast(sB.y + braw(v3.z)), wB.y, a3);
                a3 = fmaf(tanh_fast(sB.z + bl(v3.w)), wB.z, a3);
                a3 = fmaf(tanh_fast(sB.w + braw(v3.w)), wB.w, a3);
            }
#pragma unroll
            for (int o = 1; o < 16; o <<= 1) {
                a0 += __shfl_xor_sync(0xffffffffu, a0, o);
                a1 += __shfl_xor_sync(0xffffffffu, a1, o);
                a2 += __shfl_xor_sync(0xffffffffu, a2, o);
                a3 += __shfl_xor_sync(0xffffffffu, a3, o);
            }
            if (sub == 0) {
                es[bb * 64 + d0 + 0] = a0 + b3v;
                es[bb * 64 + d0 + 1] = a1 + b3v;
                es[bb * 64 + d0 + 2] = a2 + b3v;
                es[bb * 64 + d0 + 3] = a3 + b3v;
            }
        }
        __syncthreads();

        // ---- Phase C: softmax over d (no max-subtract: |e| bounded), x = a*x_t ----
        if (tid < 64) {
            const int bb = tid >> 5, lane = tid & 31;
            float e0 = es[bb * 64 + lane], e1 = es[bb * 64 + lane + 32];
            float p0 = __expf(e0), p1 = __expf(e1);
            float sm = p0 + p1;
#pragma unroll
            for (int o = 16; o; o >>= 1) sm += __shfl_xor_sync(0xffffffffu, sm, o);
            float inv = 1.f / sm;
            xs[bb * 64 + lane]      = p0 * inv * dinb[bb * 64 + lane];
            xs[bb * 64 + lane + 32] = p1 * inv * dinb[bb * 64 + lane + 32];
        }
        __syncthreads();

        // ---- Phase D: z += x.WihCol (weights from SMEM) ----
        {
            const int j = tid;
            const ulonglong2* x0 = (const ulonglong2*)xs;
            const ulonglong2* x1 = (const ulonglong2*)(xs + 64);
            ull a0 = 0, a1 = 0;
#pragma unroll
            for (int kk = 0; kk < 8; kk++) {
                uint4 w = wihs[kk * 512 + j];
                ulonglong2 pa = x0[kk * 2], pb = x0[kk * 2 + 1];
                ulonglong2 qa = x1[kk * 2], qb = x1[kk * 2 + 1];
                ull w01 = bfpair(w.x), w23 = bfpair(w.y);
                ull w45 = bfpair(w.z), w67 = bfpair(w.w);
                ffma2(a0, w01, pa.x); ffma2(a0, w23, pa.y);
                ffma2(a0, w45, pb.x); ffma2(a0, w67, pb.y);
                ffma2(a1, w01, qa.x); ffma2(a1, w23, qa.y);
                ffma2(a1, w45, qb.x); ffma2(a1, w67, qb.y);
            }
            zhs[j]       += pair_sum(a0);
            zhs[512 + j] += pair_sum(a1);
        }
        __syncthreads();

        // ---- Phase E: gates, state update, output (padded hc layout) ----
        if (tid < 256) {
            const int bb = tid >> 7, m = tid & 127;
            float iv = zhs[bb * 512 + m];
            float fv = zhs[bb * 512 + 128 + m];
            float gv = zhs[bb * 512 + 256 + m];
            float ov = zhs[bb * 512 + 384 + m];
            const int mp = m + 4 * (m >> 5);
            float c = hcp[bb * 288 + 144 + mp];
            float cn = sigf(fv) * c + sigf(iv) * tanh_ex(gv);
            float hn = sigf(ov) * tanh_ex(cn);
            hcp[bb * 288 + 144 + mp] = cn;
            hcp[bb * 288 + mp] = hn;
            out[(((size_t)(b0 + bb)) * TT + t) * HH + m] = hn;
        }
        __syncthreads();
    }
}

// ---------------- launch ----------------
extern "C" void kernel_launch(void* const* d_in, const int* in_sizes, int n_in,
                              void* d_out, int out_size) {
    const float* din = (const float*)d_in[0];
    const float* Wih = (const float*)d_in[1];
    const float* Whh = (const float*)d_in[2];
    const float* bih = (const float*)d_in[3];
    const float* bhh = (const float*)d_in[4];
    const float* W1  = (const float*)d_in[5];
    const float* b1  = (const float*)d_in[6];
    const float* W2  = (const float*)d_in[7];
    const float* b2  = (const float*)d_in[8];
    const float* W3  = (const float*)d_in[9];
    const float* b3  = (const float*)d_in[10];
    float* out = (float*)d_out;

    cudaFuncSetAttribute(fused_kernel, cudaFuncAttributeMaxDynamicSharedMemorySize, SM_TOTAL);
    fused_kernel<<<NBLK, 512, SM_TOTAL>>>(din, Wih, Whh, bih, bhh, W1, b1, W2, b2, W3, b3, out);
}

// round 12
// speedup vs baseline: 1.3417x; 1.3417x over previous
#include <cuda_runtime.h>
#include <cuda_bf16.h>

#define BB 256
#define TT 512
#define DD 64
#define HH 128
#define NBLK 128

// ---------------- device scratch (static, no allocation) ----------------
__device__ __nv_bfloat16 g_w1p[32 * 512 * 8];   // [kk][s][u], k = kk*8+u in [0,256)
__device__ __nv_bfloat16 g_wzp[24 * 512 * 8];   // [kk][j][u]: kk 0..7 Wih, 8..23 Whh
__device__ unsigned g_bar_count = 0;
__device__ unsigned g_bar_flag = 0;

// ---------------- helpers ----------------
typedef unsigned long long ull;

__device__ __forceinline__ float tanh_fast(float x) {
    float y;
    asm("tanh.approx.f32 %0, %1;" : "=f"(y) : "f"(x));
    return y;
}
__device__ __forceinline__ float tanh_ex(float x) {
    x = fminf(fmaxf(x, -15.f), 15.f);
    float e = __expf(2.f * x);
    return (e - 1.f) / (e + 1.f);
}
__device__ __forceinline__ float bl(unsigned u) { return __uint_as_float(u << 16); }
__device__ __forceinline__ float braw(unsigned u) { return __uint_as_float(u); }
__device__ __forceinline__ void ffma2(ull& acc, ull ab, ull cd) {
    asm("fma.rn.f32x2 %0, %1, %2, %0;" : "+l"(acc) : "l"(ab), "l"(cd));
}
// pair {even = u<<16, odd = u raw (tail-compensated)}
__device__ __forceinline__ ull bfpair(unsigned u) {
    ull p;
    asm("{\n\t.reg .b32 lo;\n\t"
        "shl.b32 lo, %1, 16;\n\t"
        "mov.b64 %0, {lo, %1};\n\t}" : "=l"(p) : "r"(u));
    return p;
}
__device__ __forceinline__ ull mk_pair(float lo, float hi) {
    ull p;
    asm("mov.b64 %0, {%1, %2};" : "=l"(p) : "f"(lo), "f"(hi));
    return p;
}
__device__ __forceinline__ float pair_lo(ull p) { return __uint_as_float((unsigned)p); }
__device__ __forceinline__ float pair_hi(ull p) { return __uint_as_float((unsigned)(p >> 32)); }
__device__ __forceinline__ float pair_sum(ull p) { return pair_lo(p) + pair_hi(p); }

// Tail-compensated pair pack: raw reuse of odd elem adds no error vs bf16.
__device__ __forceinline__ unsigned pack_comp(float we, float wo) {
    __nv_bfloat16 be = __float2bfloat16(we);
    unsigned below = (unsigned)*(unsigned short*)&be;
    unsigned fo = __float_as_uint(wo);
    unsigned c0 = (fo & 0xffff0000u) | below;
    unsigned cm = c0 - 0x10000u;
    unsigned cp = c0 + 0x10000u;
    float d0 = fabsf(__uint_as_float(c0) - wo);
    float dm = fabsf(__uint_as_float(cm) - wo);
    float dp = fabsf(__uint_as_float(cp) - wo);
    unsigned best = c0;
    float bd = d0;
    if (dm < bd) { best = cm; bd = dm; }
    if (dp < bd) { best = cp; }
    return best;
}

// gate-interleave permutation for j in [0,512): p = (j&127)*4 + (j>>7)
__device__ __forceinline__ int permj(int j) { return ((j & 127) << 2) | (j >> 7); }

// ---------------- smem layout ----------------
#define S2STRIDE 552
#define SM_S2_BYTES (2 * 64 * S2STRIDE * 2)      // 141312
#define SM_WIH_BYTES (8 * 512 * 16)              // 65536
#define SM_FLOATS (512 + 1024 + 1024 + 128 + 128 + 512 + 512 + 512 + 128)  // 4480
#define SM_TOTAL (SM_S2_BYTES + SM_WIH_BYTES + SM_FLOATS * 4)              // 224768

// ---------------- the one kernel ----------------
__global__ void __launch_bounds__(512, 1) fused_kernel(
    const float* __restrict__ din, const float* __restrict__ Wih,
    const float* __restrict__ Whh, const float* __restrict__ bih,
    const float* __restrict__ bhh, const float* __restrict__ W1,
    const float* __restrict__ b1, const float* __restrict__ W2,
    const float* __restrict__ b2, const float* __restrict__ W3,
    const float* __restrict__ b3, float* __restrict__ out) {
    extern __shared__ char smraw[];
    __nv_bfloat16* s2s = (__nv_bfloat16*)smraw;                 // [2*64][552]
    uint4* wihs = (uint4*)(smraw + SM_S2_BYTES);                // [8*512] uint4, gate-interleaved
    float* hc   = (float*)(smraw + SM_S2_BYTES + SM_WIH_BYTES); // [2][256]: h then c
    float* s1s  = hc + 512;                                      // [2][512]
    float* zhs  = s1s + 1024;                                    // [2][512] gate-interleaved
    float* xs   = zhs + 1024;                                    // [2][64]
    float* es   = xs + 128;                                      // [2][64]
    float* w3s  = es + 128;                                      // [512]
    float* b1s  = w3s + 512;                                     // [512]
    float* bzs  = b1s + 512;                                     // [512]
    float* dinb = bzs + 512;                                     // [2][64]

    const int tid = threadIdx.x;
    const int b0 = blockIdx.x * 2;

    // ======== STAGE 1: pack weights (grid-strided, pair-compensated) ========
    {
        int gidx = blockIdx.x * 512 + tid;
        int gstride = NBLK * 512;
        unsigned* w1d = (unsigned*)g_w1p;
        for (int i = gidx; i < 32 * 512 * 4; i += gstride) {
            int uu2 = (i & 3) * 2, s = (i >> 2) & 511, kk = i >> 11;
            int k0 = kk * 8 + uu2;
            w1d[i] = pack_comp(W1[s * 256 + k0], W1[s * 256 + k0 + 1]);
        }
        unsigned* wzd = (unsigned*)g_wzp;
        for (int i = gidx; i < 24 * 512 * 4; i += gstride) {
            int uu2 = (i & 3) * 2, j = (i >> 2) & 511, kk = i >> 11;
            int k0 = kk * 8 + uu2;
            float v0 = (k0 < 64) ? Wih[j * 64 + k0] : Whh[j * 128 + (k0 - 64)];
            float v1 = (k0 + 1 < 64) ? Wih[j * 64 + k0 + 1] : Whh[j * 128 + (k0 + 1 - 64)];
            wzd[i] = pack_comp(v0, v1);
        }
    }
    // grid barrier (128 blocks, all resident)
    __syncthreads();
    if (tid == 0) {
        unsigned f0 = *((volatile unsigned*)&g_bar_flag);
        __threadfence();
        unsigned old = atomicAdd(&g_bar_count, 1);
        if (old == NBLK - 1) {
            g_bar_count = 0;
            __threadfence();
            atomicAdd(&g_bar_flag, 1);
        } else {
            while (*((volatile unsigned*)&g_bar_flag) == f0) { __nanosleep(64); }
        }
        __threadfence();
    }
    __syncthreads();

    // ======== STAGE 2: s2[b,d,s] into SMEM ========
    {
        float* w2st  = (float*)(smraw + SM_S2_BYTES);  // [32][514] staging
        float* dinst = w2st + 32 * 514;                 // [32][64]
        const int lane = tid & 31, sgrp = tid >> 5;
        const int d0 = lane * 2, sbase = sgrp * 32;

        for (int bb = 0; bb < 2; bb++) {
            const int b = b0 + bb;
            ull acc[2][16];
#pragma unroll
            for (int p = 0; p < 16; p++) {
                float2 bp = *(const float2*)(b2 + sbase + 2 * p);
                acc[0][p] = mk_pair(bp.x, bp.y);
                acc[1][p] = acc[0][p];
            }
            for (int tc = 0; tc < 16; tc++) {
                const int t0 = tc * 32;
                __syncthreads();
                for (int i = tid; i < 32 * 512; i += 512) {
                    int tt = i & 31, sl = i >> 5;
                    w2st[tt * 514 + sl] = W2[(size_t)sl * TT + t0 + tt];
                }
                for (int i = tid; i < 32 * 64; i += 512) {
                    int tt = i >> 6, dd = i & 63;
                    dinst[tt * 64 + dd] = din[((size_t)b * TT + t0 + tt) * DD + dd];
                }
                __syncthreads();
#pragma unroll 4
                for (int tt = 0; tt < 32; tt++) {
                    float2 av = *(const float2*)&dinst[tt * 64 + d0];
                    ull ax = mk_pair(av.x, av.x);
                    ull ay = mk_pair(av.y, av.y);
                    const ull* wrow = (const ull*)(w2st + tt * 514 + sbase);
#pragma unroll
                    for (int p = 0; p < 16; p++) {
                        ull wp = wrow[p];
                        ffma2(acc[0][p], wp, ax);
                        ffma2(acc[1][p], wp, ay);
                    }
                }
            }
#pragma unroll
            for (int dl = 0; dl < 2; dl++) {
                unsigned* row = (unsigned*)(s2s + (size_t)(bb * 64 + d0 + dl) * S2STRIDE + sbase);
#pragma unroll
                for (int p = 0; p < 16; p++)
                    row[p] = pack_comp(pair_lo(acc[dl][p]), pair_hi(acc[dl][p]));
            }
        }
    }
    __syncthreads();

    // ======== STAGE 3: init scan constants ========
    w3s[tid] = W3[tid];
    b1s[tid] = b1[tid];
    bzs[tid] = bih[tid] + bhh[tid];
    hc[tid] = 0.f;
    {
        // Wih (kk 0..7) into SMEM, gate-interleaved columns
        const uint4* src = (const uint4*)g_wzp;
        for (int i = tid; i < 8 * 512; i += 512) {
            int kk = i >> 9, j = i & 511;
            wihs[kk * 512 + permj(j)] = src[i];
        }
    }
    __syncthreads();
    const float b3v = b3[0];

    // ======== STAGE 4: the scan (4 barriers/step) ========
    for (int t = 0; t < TT; t++) {
        // prefetch din[., t, .] for phase C (latency hidden behind phase A)
        float dval = 0.f;
        if (tid < 128) {
            int bb = tid >> 6, dd = tid & 63;
            dval = din[((size_t)(b0 + bb) * TT + t) * DD + dd];
        }
        // ---- Phase A: s1 = [h;c].W1col + b1 ; zh = h.WhhCol + bz (permuted store) ----
        {
            const int s = tid;
            const uint4* w1p = (const uint4*)g_w1p;
            const uint4* whp = (const uint4*)g_wzp + 8 * 512;
            const ulonglong2* h0 = (const ulonglong2*)hc;
            const ulonglong2* h1 = (const ulonglong2*)(hc + 256);
            ull aW0 = 0, aW1 = 0, aH0 = 0, aH1 = 0;
#pragma unroll 4
            for (int kk = 0; kk < 16; kk++) {
                uint4 w = w1p[kk * 512 + s];
                uint4 v = whp[kk * 512 + s];
                ulonglong2 pa = h0[kk * 2], pb = h0[kk * 2 + 1];
                ulonglong2 qa = h1[kk * 2], qb = h1[kk * 2 + 1];
                ull w01 = bfpair(w.x), w23 = bfpair(w.y);
                ull w45 = bfpair(w.z), w67 = bfpair(w.w);
                ull v01 = bfpair(v.x), v23 = bfpair(v.y);
                ull v45 = bfpair(v.z), v67 = bfpair(v.w);
                ffma2(aW0, w01, pa.x); ffma2(aW0, w23, pa.y);
                ffma2(aW0, w45, pb.x); ffma2(aW0, w67, pb.y);
                ffma2(aW1, w01, qa.x); ffma2(aW1, w23, qa.y);
                ffma2(aW1, w45, qb.x); ffma2(aW1, w67, qb.y);
                ffma2(aH0, v01, pa.x); ffma2(aH0, v23, pa.y);
                ffma2(aH0, v45, pb.x); ffma2(aH0, v67, pb.y);
                ffma2(aH1, v01, qa.x); ffma2(aH1, v23, qa.y);
                ffma2(aH1, v45, qb.x); ffma2(aH1, v67, qb.y);
            }
#pragma unroll 4
            for (int kk = 16; kk < 32; kk++) {
                uint4 w = w1p[kk * 512 + s];
                ulonglong2 pa = h0[kk * 2], pb = h0[kk * 2 + 1];
                ulonglong2 qa = h1[kk * 2], qb = h1[kk * 2 + 1];
                ull w01 = bfpair(w.x), w23 = bfpair(w.y);
                ull w45 = bfpair(w.z), w67 = bfpair(w.w);
                ffma2(aW0, w01, pa.x); ffma2(aW0, w23, pa.y);
                ffma2(aW0, w45, pb.x); ffma2(aW0, w67, pb.y);
                ffma2(aW1, w01, qa.x); ffma2(aW1, w23, qa.y);
                ffma2(aW1, w45, qb.x); ffma2(aW1, w67, qb.y);
            }
            s1s[s]       = pair_sum(aW0) + b1s[s];
            s1s[512 + s] = pair_sum(aW1) + b1s[s];
            const int jp = permj(s);
            float bz = bzs[s];
            zhs[jp]       = pair_sum(aH0) + bz;
            zhs[512 + jp] = pair_sum(aH1) + bz;
        }
        if (tid < 128) dinb[tid] = dval;
        __syncthreads();

        // ---- Phase B: e[b][d] = sum_s tanh(s1+s2)*w3 + b3 (16 subs x 4 rows) ----
        {
            const int sub = tid & 15, grp = tid >> 4;
            const int bb = grp >> 4, d0 = (grp & 15) * 4;
            const __nv_bfloat16* rowbase = s2s + (size_t)(bb * 64 + d0) * S2STRIDE;
            const uint4* r0 = (const uint4*)(rowbase);
            const uint4* r1 = (const uint4*)(rowbase + S2STRIDE);
            const uint4* r2 = (const uint4*)(rowbase + 2 * S2STRIDE);
            const uint4* r3 = (const uint4*)(rowbase + 3 * S2STRIDE);
            const float4* s1f = (const float4*)(s1s + bb * 512);
            const float4* w3f = (const float4*)w3s;
            float a0 = 0.f, a1 = 0.f, a2 = 0.f, a3 = 0.f;
#pragma unroll
            for (int i = 0; i < 4; i++) {
                const int q = sub + 16 * i;
                float4 sA = s1f[2 * q], sB = s1f[2 * q + 1];
                float4 wA = w3f[2 * q], wB = w3f[2 * q + 1];
                uint4 v0 = r0[q], v1 = r1[q], v2 = r2[q], v3 = r3[q];
                a0 = fmaf(tanh_fast(sA.x + bl(v0.x)), wA.x, a0);
                a0 = fmaf(tanh_fast(sA.y + braw(v0.x)), wA.y, a0);
                a0 = fmaf(tanh_fast(sA.z + bl(v0.y)), wA.z, a0);
                a0 = fmaf(tanh_fast(sA.w + braw(v0.y)), wA.w, a0);
                a0 = fmaf(tanh_fast(sB.x + bl(v0.z)), wB.x, a0);
                a0 = fmaf(tanh_fast(sB.y + braw(v0.z)), wB.y, a0);
                a0 = fmaf(tanh_fast(sB.z + bl(v0.w)), wB.z, a0);
                a0 = fmaf(tanh_fast(sB.w + braw(v0.w)), wB.w, a0);
                a1 = fmaf(tanh_fast(sA.x + bl(v1.x)), wA.x, a1);
                a1 = fmaf(tanh_fast(sA.y + braw(v1.x)), wA.y, a1);
                a1 = fmaf(tanh_fast(sA.z + bl(v1.y)), wA.z, a1);
                a1 = fmaf(tanh_fast(sA.w + braw(v1.y)), wA.w, a1);
                a1 = fmaf(tanh_fast(sB.x + bl(v1.z)), wB.x, a1);
                a1 = fmaf(tanh_fast(sB.y + braw(v1.z)), wB.y, a1);
                a1 = fmaf(tanh_fast(sB.z + bl(v1.w)), wB.z, a1);
                a1 = fmaf(tanh_fast(sB.w + braw(v1.w)), wB.w, a1);
                a2 = fmaf(tanh_fast(sA.x + bl(v2.x)), wA.x, a2);
                a2 = fmaf(tanh_fast(sA.y + braw(v2.x)), wA.y, a2);
                a2 = fmaf(tanh_fast(sA.z + bl(v2.y)), wA.z, a2);
                a2 = fmaf(tanh_fast(sA.w + braw(v2.y)), wA.w, a2);
                a2 = fmaf(tanh_fast(sB.x + bl(v2.z)), wB.x, a2);
                a2 = fmaf(tanh_fast(sB.y + braw(v2.z)), wB.y, a2);
                a2 = fmaf(tanh_fast(sB.z + bl(v2.w)), wB.z, a2);
                a2 = fmaf(tanh_fast(sB.w + braw(v2.w)), wB.w, a2);
                a3 = fmaf(tanh_fast(sA.x + bl(v3.x)), wA.x, a3);
                a3 = fmaf(tanh_fast(sA.y + braw(v3.x)), wA.y, a3);
                a3 = fmaf(tanh_fast(sA.z + bl(v3.y)), wA.z, a3);
                a3 = fmaf(tanh_fast(sA.w + braw(v3.y)), wA.w, a3);
                a3 = fmaf(tanh_fast(sB.x + bl(v3.z)), wB.x, a3);
                a3 = fmaf(tanh_fast(sB.y + braw(v3.z)), wB.y, a3);
                a3 = fmaf(tanh_fast(sB.z + bl(v3.w)), wB.z, a3);
                a3 = fmaf(tanh_fast(sB.w + braw(v3.w)), wB.w, a3);
            }
#pragma unroll
            for (int o = 1; o < 16; o <<= 1) {
                a0 += __shfl_xor_sync(0xffffffffu, a0, o);
                a1 += __shfl_xor_sync(0xffffffffu, a1, o);
                a2 += __shfl_xor_sync(0xffffffffu, a2, o);
                a3 += __shfl_xor_sync(0xffffffffu, a3, o);
            }
            if (sub == 0) {
                es[bb * 64 + d0 + 0] = a0 + b3v;
                es[bb * 64 + d0 + 1] = a1 + b3v;
                es[bb * 64 + d0 + 2] = a2 + b3v;
                es[bb * 64 + d0 + 3] = a3 + b3v;
            }
        }
        __syncthreads();

        // ---- Phase C: softmax over d (no max-subtract: |e| bounded), x = a*x_t ----
        if (tid < 64) {
            const int bb = tid >> 5, lane = tid & 31;
            float e0 = es[bb * 64 + lane], e1 = es[bb * 64 + lane + 32];
            float p0 = __expf(e0), p1 = __expf(e1);
            float sm = p0 + p1;
#pragma unroll
            for (int o = 16; o; o >>= 1) sm += __shfl_xor_sync(0xffffffffu, sm, o);
            float inv = 1.f / sm;
            xs[bb * 64 + lane]      = p0 * inv * dinb[bb * 64 + lane];
            xs[bb * 64 + lane + 32] = p1 * inv * dinb[bb * 64 + lane + 32];
        }
        __syncthreads();

        // ---- Phase D+E fused: z = x.WihCol + zh; gates; state update; output ----
        {
            const int g = tid & 3, m = tid >> 2;       // gate g of hidden unit m
            const ulonglong2* x0 = (const ulonglong2*)xs;
            const ulonglong2* x1 = (const ulonglong2*)(xs + 64);
            ull a0 = 0, a1 = 0;
#pragma unroll
            for (int kk = 0; kk < 8; kk++) {
                uint4 w = wihs[kk * 512 + tid];        // gate-interleaved: conflict-free
                ulonglong2 pa = x0[kk * 2], pb = x0[kk * 2 + 1];
                ulonglong2 qa = x1[kk * 2], qb = x1[kk * 2 + 1];
                ull w01 = bfpair(w.x), w23 = bfpair(w.y);
                ull w45 = bfpair(w.z), w67 = bfpair(w.w);
                ffma2(a0, w01, pa.x); ffma2(a0, w23, pa.y);
                ffma2(a0, w45, pb.x); ffma2(a0, w67, pb.y);
                ffma2(a1, w01, qa.x); ffma2(a1, w23, qa.y);
                ffma2(a1, w45, qb.x); ffma2(a1, w67, qb.y);
            }
            float z0 = pair_sum(a0) + zhs[tid];        // permuted zh: conflict-free
            float z1 = pair_sum(a1) + zhs[512 + tid];
            // branch-free nonlinearity: sig(z) = 0.5*(1 + tanh(z/2))
            const bool isg = (g == 2);
            float t0v = tanh_ex(isg ? z0 : 0.5f * z0);
            float t1v = tanh_ex(isg ? z1 : 0.5f * z1);
            float nv0 = isg ? t0v : fmaf(0.5f, t0v, 0.5f);
            float nv1 = isg ? t1v : fmaf(0.5f, t1v, 0.5f);
            const int base = (tid & 31) & ~3;
            float si0 = __shfl_sync(0xffffffffu, nv0, base);
            float sf0 = __shfl_sync(0xffffffffu, nv0, base + 1);
            float tg0 = __shfl_sync(0xffffffffu, nv0, base + 2);
            float so0 = __shfl_sync(0xffffffffu, nv0, base + 3);
            float si1 = __shfl_sync(0xffffffffu, nv1, base);
            float sf1 = __shfl_sync(0xffffffffu, nv1, base + 1);
            float tg1 = __shfl_sync(0xffffffffu, nv1, base + 2);
            float so1 = __shfl_sync(0xffffffffu, nv1, base + 3);
            if (g == 0) {
                float c0 = hc[128 + m];
                float cn0 = sf0 * c0 + si0 * tg0;
                float hn0 = so0 * tanh_ex(cn0);
                hc[128 + m] = cn0;
                hc[m] = hn0;
                out[((size_t)b0 * TT + t) * HH + m] = hn0;
                float c1 = hc[256 + 128 + m];
                float cn1 = sf1 * c1 + si1 * tg1;
                float hn1 = so1 * tanh_ex(cn1);
                hc[256 + 128 + m] = cn1;
                hc[256 + m] = hn1;
                out[((size_t)(b0 + 1) * TT + t) * HH + m] = hn1;
            }
        }
        __syncthreads();
    }
}

// ---------------- launch ----------------
extern "C" void kernel_launch(void* const* d_in, const int* in_sizes, int n_in,
                              void* d_out, int out_size) {
    const float* din = (const float*)d_in[0];
    const float* Wih = (const float*)d_in[1];
    const float* Whh = (const float*)d_in[2];
    const float* bih = (const float*)d_in[3];
    const float* bhh = (const float*)d_in[4];
    const float* W1  = (const float*)d_in[5];
    const float* b1  = (const float*)d_in[6];
    const float* W2  = (const float*)d_in[7];
    const float* b2  = (const float*)d_in[8];
    const float* W3  = (const float*)d_in[9];
    const float* b3  = (const float*)d_in[10];
    float* out = (float*)d_out;

    cudaFuncSetAttribute(fused_kernel, cudaFuncAttributeMaxDynamicSharedMemorySize, SM_TOTAL);
    fused_kernel<<<NBLK, 512, SM_TOTAL>>>(din, Wih, Whh, bih, bhh, W1, b1, W2, b2, W3, b3, out);
}